// round 5
// baseline (speedup 1.0000x reference)
#include <cuda_runtime.h>
#include <cuda_bf16.h>
#include <math.h>

// Problem constants (fixed by setup_inputs): B=8, C=64, H=W=128, 3x3 unfold pad=1.
#define BATCH 8
#define CHANS 64
#define HDIM 128
#define WDIM 128
#define TILE_W 32        // 32-wide x 8-tall spatial tile per CTA
#define TILE_H 8
#define HALO_W 34        // TILE_W + 2
#define HALO_H 10        // TILE_H + 2
#define HALO2 (HALO_W * HALO_H)   // 340
#define NTHREADS 128     // warp = one 32-wide row strip; thread owns 2x1 pixel pair

// Shared memory: fused halo tile [C][10][34] (fe_lv streamed from gmem/L2)
#define SMEM_FLOATS (CHANS * HALO2)     // 21760
#define SMEM_BYTES  (SMEM_FLOATS * 4)   // 87040 B -> 2 CTAs/SM

__global__ __launch_bounds__(NTHREADS, 2)
void asfre_kernel(const float* __restrict__ fe_lv,
                  const float* __restrict__ fused,
                  float* __restrict__ out)
{
    extern __shared__ float s_fused[];   // [c][y][x], y in [0,10), x in [0,34)

    const int tid = threadIdx.x;
    const int tx  = tid & 31;            // 0..31  (full warp = one row strip)
    const int tyy = tid >> 5;            // 0..3  -> pixel rows 2*tyy, 2*tyy+1
    const int w0  = blockIdx.x * TILE_W;
    const int h0  = blockIdx.y * TILE_H;
    const int b   = blockIdx.z;

    const size_t plane = (size_t)HDIM * WDIM;
    const float* fbase  = fused + (size_t)b * CHANS * plane;
    const float* febase = fe_lv + (size_t)b * CHANS * plane;

    // ---- Stage fused 10x34 halo tile for all 64 channels (zero-pad OOB) ----
    // Hoisted index math: each thread owns halo positions {tid, tid+128, tid+256};
    // the channel loop is pure pointer increments + predicated LDG.
    {
        long goff[3];
        bool val[3];
        #pragma unroll
        for (int s = 0; s < 3; ++s) {
            int p = tid + s * NTHREADS;          // 0..383 (340 valid)
            int y = p / HALO_W;
            int x = p - y * HALO_W;
            int gh = h0 + y - 1;
            int gw = w0 + x - 1;
            val[s]  = (p < HALO2) && ((unsigned)gh < HDIM) && ((unsigned)gw < WDIM);
            goff[s] = (long)gh * WDIM + gw;
        }
        const bool wr2 = (tid + 2 * NTHREADS) < HALO2;   // tid < 84

        const float* g0 = fbase + goff[0];
        const float* g1 = fbase + goff[1];
        const float* g2 = fbase + goff[2];
        float* s0 = s_fused + tid;
        float* s1 = s_fused + tid + NTHREADS;
        float* s2 = s_fused + (wr2 ? tid + 2 * NTHREADS : 0);

        #pragma unroll 4
        for (int c = 0; c < CHANS; ++c) {
            float v0 = val[0] ? __ldg(g0) : 0.0f;
            float v1 = val[1] ? __ldg(g1) : 0.0f;
            *s0 = v0;  s0 += HALO2;  g0 += plane;
            *s1 = v1;  s1 += HALO2;  g1 += plane;
            if (wr2) {
                float v2 = val[2] ? __ldg(g2) : 0.0f;
                *s2 = v2;  s2 += HALO2;  g2 += plane;
            }
        }
    }
    __syncthreads();

    const int py0 = 2 * tyy;                       // this thread's pixel rows: py0, py0+1
    // Pixel (py,px) window = halo rows py..py+2, cols px..px+2.
    const float* spbase = s_fused + py0 * HALO_W + tx;
    const float* feb    = febase + (size_t)(h0 + py0) * WDIM + (w0 + tx);

    // ---- Pass 1: squared Euclidean distances over C for both pixels ----
    float acc0[9], acc1[9];
    #pragma unroll
    for (int k = 0; k < 9; ++k) { acc0[k] = 0.0f; acc1[k] = 0.0f; }

    {
        const float* sp  = spbase;
        const float* fe  = feb;
        #pragma unroll 4
        for (int c = 0; c < CHANS; ++c) {
            float v[4][3];
            #pragma unroll
            for (int r = 0; r < 4; ++r)
                #pragma unroll
                for (int j = 0; j < 3; ++j)
                    v[r][j] = sp[r * HALO_W + j];  // conflict-free: 32 consecutive lanes
            const float fe0 = __ldg(fe);
            const float fe1 = __ldg(fe + WDIM);
            #pragma unroll
            for (int i = 0; i < 3; ++i) {
                #pragma unroll
                for (int j = 0; j < 3; ++j) {
                    float d0 = v[i][j]     - fe0;
                    float d1 = v[i + 1][j] - fe1;
                    acc0[i * 3 + j] = fmaf(d0, d0, acc0[i * 3 + j]);
                    acc1[i * 3 + j] = fmaf(d1, d1, acc1[i * 3 + j]);
                }
            }
            sp += HALO2;
            fe += plane;
        }
    }

    // ---- Softmax over 9 neighbors of -sqrt(acc), min-shifted for stability ----
    float wk0[9], wk1[9];
    {
        float d0[9], d1[9];
        float m0 = 3.402823466e+38f, m1 = m0;
        #pragma unroll
        for (int k = 0; k < 9; ++k) {
            d0[k] = sqrtf(acc0[k]);  m0 = fminf(m0, d0[k]);
            d1[k] = sqrtf(acc1[k]);  m1 = fminf(m1, d1[k]);
        }
        float s0 = 0.0f, s1 = 0.0f;
        #pragma unroll
        for (int k = 0; k < 9; ++k) {
            wk0[k] = __expf(m0 - d0[k]);  s0 += wk0[k];
            wk1[k] = __expf(m1 - d1[k]);  s1 += wk1[k];
        }
        const float i0 = 1.0f / s0, i1 = 1.0f / s1;
        #pragma unroll
        for (int k = 0; k < 9; ++k) { wk0[k] *= i0; wk1[k] *= i1; }
    }

    // ---- Pass 2: weighted neighbor sum per channel + residual ----
    {
        const float* sp = spbase;
        const float* fe = feb;
        float* ob = out + (size_t)b * CHANS * plane
                        + (size_t)(h0 + py0) * WDIM + (w0 + tx);
        #pragma unroll 4
        for (int c = 0; c < CHANS; ++c) {
            float v[4][3];
            #pragma unroll
            for (int r = 0; r < 4; ++r)
                #pragma unroll
                for (int j = 0; j < 3; ++j)
                    v[r][j] = sp[r * HALO_W + j];
            float r0 = __ldg(fe);              // residual = fe_lv
            float r1 = __ldg(fe + WDIM);
            #pragma unroll
            for (int i = 0; i < 3; ++i) {
                #pragma unroll
                for (int j = 0; j < 3; ++j) {
                    r0 = fmaf(wk0[i * 3 + j], v[i][j],     r0);
                    r1 = fmaf(wk1[i * 3 + j], v[i + 1][j], r1);
                }
            }
            ob[0]    = r0;                     // 128B coalesced per warp
            ob[WDIM] = r1;
            sp += HALO2;
            fe += plane;
            ob += plane;
        }
    }
}

extern "C" void kernel_launch(void* const* d_in, const int* in_sizes, int n_in,
                              void* d_out, int out_size)
{
    const float* fe_lv = (const float*)d_in[0];
    const float* fused = (const float*)d_in[1];
    float* out = (float*)d_out;

    // Idempotent, non-stream, capture-safe; no static guard (rigor rules).
    cudaFuncSetAttribute(asfre_kernel,
                         cudaFuncAttributeMaxDynamicSharedMemorySize, SMEM_BYTES);

    dim3 grid(WDIM / TILE_W, HDIM / TILE_H, BATCH);  // 4 x 16 x 8 = 512 CTAs
    asfre_kernel<<<grid, NTHREADS, SMEM_BYTES>>>(fe_lv, fused, out);
}

// round 8
// speedup vs baseline: 2.5071x; 2.5071x over previous
#include <cuda_runtime.h>
#include <cuda_bf16.h>
#include <cstdint>
#include <math.h>

// Problem constants (fixed by setup_inputs): B=8, C=64, H=W=128, 3x3 unfold pad=1.
#define BATCH 8
#define CHANS 64
#define HDIM 128
#define WDIM 128
#define TILE_W 32        // 32-wide x 8-tall spatial tile per CTA
#define TILE_H 8
#define HALO_W 34        // TILE_W + 2
#define HALO_H 10        // TILE_H + 2
#define HALO2 (HALO_W * HALO_H)       // 340
#define NTHREADS 256     // 1 pixel per thread; warp = one 32-wide row
#define CHUNK 16         // channels staged per chunk
#define NCHUNK (CHANS / CHUNK)        // 4
#define CH_FLOATS (CHUNK * HALO2)     // 5440 floats = 21760 B per buffer
#define SMEM_BYTES (2 * CH_FLOATS * 4) // 43520 B (double buffer) -> 4 CTAs/SM

#define CP_COMMIT() asm volatile("cp.async.commit_group;")

// Stage one 16-channel chunk of the fused halo tile into smem via cp.async.
// Warp w stages channels {2w, 2w+1}. Zero-fill OOB via src_size=0.
__device__ __forceinline__ void stage_chunk(
    const float* __restrict__ fbase, float* buf, int c0,
    int h0, int w0, int wid, int lane,
    unsigned rowmask, bool colok, bool x33ok)
{
    const size_t plane = (size_t)HDIM * WDIM;
    unsigned int sbase = (unsigned int)__cvta_generic_to_shared(buf);
    #pragma unroll
    for (int cc = 0; cc < 2; ++cc) {
        const int ch = wid * 2 + cc;                 // 0..15 within chunk
        const float* g = fbase + (size_t)(c0 + ch) * plane
                               + (long)(h0 - 1) * WDIM + (w0 - 1 + lane);
        unsigned int d = sbase + (unsigned int)(ch * HALO2 + lane) * 4u;
        #pragma unroll
        for (int y = 0; y < HALO_H; ++y) {
            int sz = (((rowmask >> y) & 1u) && colok) ? 4 : 0;
            asm volatile("cp.async.ca.shared.global [%0], [%1], 4, %2;"
                         :: "r"(d), "l"(g), "r"(sz));
            d += HALO_W * 4;
            g += WDIM;
        }
        // Remainder: halo cols x=32,33 for all 10 rows (20 positions, lanes 0..19)
        if (lane < 20) {
            const int yy = lane >> 1;
            const int xx = 32 + (lane & 1);
            int ok = (((rowmask >> yy) & 1u) && ((xx == 32) || x33ok)) ? 4 : 0;
            const float* gr = fbase + (size_t)(c0 + ch) * plane
                                    + (long)(h0 - 1 + yy) * WDIM + (w0 - 1 + xx);
            unsigned int dr = sbase + (unsigned int)(ch * HALO2 + yy * HALO_W + xx) * 4u;
            asm volatile("cp.async.ca.shared.global [%0], [%1], 4, %2;"
                         :: "r"(dr), "l"(gr), "r"(ok));
        }
    }
}

__global__ __launch_bounds__(NTHREADS, 4)
void asfre_kernel(const float* __restrict__ fe_lv,
                  const float* __restrict__ fused,
                  float* __restrict__ out)
{
    extern __shared__ float smem[];
    float* bufs[2] = { smem, smem + CH_FLOATS };

    const int tid  = threadIdx.x;
    const int tx   = tid & 31;           // 0..31 (warp = one 32-wide pixel row)
    const int ty   = tid >> 5;           // 0..7
    const int lane = tx;
    const int wid  = ty;                 // warp id == pixel row id
    const int w0   = blockIdx.x * TILE_W;
    const int h0   = blockIdx.y * TILE_H;
    const int b    = blockIdx.z;

    const size_t plane = (size_t)HDIM * WDIM;
    const float* fbase  = fused + (size_t)b * CHANS * plane;
    const float* febase = fe_lv + (size_t)b * CHANS * plane;

    // Halo validity, hoisted once: rowmask bit y = row (h0-1+y) in range.
    const unsigned rowmask = 0x1FEu | (h0 > 0 ? 1u : 0u) | (h0 < (HDIM - TILE_H) ? 0x200u : 0u);
    const bool colok = (lane > 0) || (w0 > 0);       // halo col x=lane -> gw=w0+lane-1
    const bool x33ok = (w0 + 32) < WDIM;             // halo col x=33 -> gw=w0+32

    // ---------------- Pass 1: distances (chunk-pipelined) ----------------
    float acc[9];
    #pragma unroll
    for (int k = 0; k < 9; ++k) acc[k] = 0.0f;

    const float* fe_run = febase + (size_t)(h0 + ty) * WDIM + (w0 + tx);

    stage_chunk(fbase, bufs[0], 0, h0, w0, wid, lane, rowmask, colok, x33ok);
    CP_COMMIT();
    #pragma unroll
    for (int k = 0; k < NCHUNK; ++k) {
        if (k + 1 < NCHUNK) {
            stage_chunk(fbase, bufs[(k + 1) & 1], (k + 1) * CHUNK,
                        h0, w0, wid, lane, rowmask, colok, x33ok);
            CP_COMMIT();
            asm volatile("cp.async.wait_group 1;");
        } else {
            asm volatile("cp.async.wait_group 0;");
        }
        __syncthreads();
        const float* sb = bufs[k & 1];
        #pragma unroll
        for (int ch = 0; ch < CHUNK; ++ch) {
            const float* sp = sb + ch * HALO2 + ty * HALO_W + tx;
            const float fe = __ldg(fe_run);  fe_run += plane;
            #pragma unroll
            for (int i = 0; i < 3; ++i)
                #pragma unroll
                for (int j = 0; j < 3; ++j) {
                    float d = sp[i * HALO_W + j] - fe;
                    acc[i * 3 + j] = fmaf(d, d, acc[i * 3 + j]);
                }
        }
        __syncthreads();
    }

    // ---------------- Softmax over 9 neighbors of -sqrt(acc) ----------------
    float wk[9];
    {
        float dst[9];
        float m = 3.402823466e+38f;
        #pragma unroll
        for (int k = 0; k < 9; ++k) { dst[k] = sqrtf(acc[k]); m = fminf(m, dst[k]); }
        float s = 0.0f;
        #pragma unroll
        for (int k = 0; k < 9; ++k) { wk[k] = __expf(m - dst[k]); s += wk[k]; }
        const float inv = 1.0f / s;
        #pragma unroll
        for (int k = 0; k < 9; ++k) wk[k] *= inv;
    }

    // ---------------- Pass 2: weighted sum + residual (restage chunks) ----------------
    const float* fe_run2 = febase + (size_t)(h0 + ty) * WDIM + (w0 + tx);
    float* out_run = out + (size_t)b * CHANS * plane
                         + (size_t)(h0 + ty) * WDIM + (w0 + tx);

    stage_chunk(fbase, bufs[0], 0, h0, w0, wid, lane, rowmask, colok, x33ok);
    CP_COMMIT();
    #pragma unroll
    for (int k = 0; k < NCHUNK; ++k) {
        if (k + 1 < NCHUNK) {
            stage_chunk(fbase, bufs[(k + 1) & 1], (k + 1) * CHUNK,
                        h0, w0, wid, lane, rowmask, colok, x33ok);
            CP_COMMIT();
            asm volatile("cp.async.wait_group 1;");
        } else {
            asm volatile("cp.async.wait_group 0;");
        }
        __syncthreads();
        const float* sb = bufs[k & 1];
        #pragma unroll
        for (int ch = 0; ch < CHUNK; ++ch) {
            const float* sp = sb + ch * HALO2 + ty * HALO_W + tx;
            float r = __ldg(fe_run2);  fe_run2 += plane;   // residual = fe_lv
            #pragma unroll
            for (int i = 0; i < 3; ++i)
                #pragma unroll
                for (int j = 0; j < 3; ++j)
                    r = fmaf(wk[i * 3 + j], sp[i * HALO_W + j], r);
            *out_run = r;  out_run += plane;               // 128B coalesced per warp
        }
        __syncthreads();
    }
}

extern "C" void kernel_launch(void* const* d_in, const int* in_sizes, int n_in,
                              void* d_out, int out_size)
{
    const float* fe_lv = (const float*)d_in[0];
    const float* fused = (const float*)d_in[1];
    float* out = (float*)d_out;

    // Capture-safe, idempotent attribute setup (no static guards).
    cudaFuncSetAttribute(asfre_kernel,
                         cudaFuncAttributeMaxDynamicSharedMemorySize, SMEM_BYTES);
    cudaFuncSetAttribute(asfre_kernel,
                         cudaFuncAttributePreferredSharedMemoryCarveout, 100);

    dim3 grid(WDIM / TILE_W, HDIM / TILE_H, BATCH);  // 4 x 16 x 8 = 512 CTAs
    asfre_kernel<<<grid, NTHREADS, SMEM_BYTES>>>(fe_lv, fused, out);
}